// round 6
// baseline (speedup 1.0000x reference)
#include <cuda_runtime.h>
#include <cuda_bf16.h>
#include <mma.h>
#include <math.h>

using namespace nvcuda;

// ---------------------------------------------------------------------------
// MegNet layer. Tensor-core (bf16 split, fp32 accum) persistent-CTA version.
// Inputs (metadata order):
//  0 bonds[E,32] f32, 1 bond_atom_1[E] i32, 2 bond_atom_2[E] i32,
//  3 atoms[N,32] f32, 4 state[1,32] f32,
//  5..10  e_w1[128,64] e_b1[64] e_w2[64,64] e_b2[64] e_w3[64,32] e_b3[32]
// 11..16  v_w1[96,64]  v_b1     v_w2        v_b2     v_w3        v_b3
// 17..22  u_w1[96,64]  u_b1     u_w2        u_b2     u_w3        u_b3
// Output: concat(bonds_new[E,32], atoms_new[N,32], state_new[1,32]) f32
//
// Numerics: every GEMM operand x is split x = hi + lo with hi = bf16(x),
// lo = bf16(x - hi). Product computed as hi*whi + hi*wlo + lo*whi in fp32
// accumulators -> relative error ~1e-5 (dropped lo*wlo term ~2^-18).
// ---------------------------------------------------------------------------

#define MAXN 100000
#define PERSISTENT_GRID 152   // GB300: 152 SMs, 1 CTA/SM at this smem size

__device__ float g_b2a[(size_t)MAXN * 32];
__device__ float g_cnt[MAXN];
__device__ float g_bond_sum[32];
__device__ float g_atom_sum[32];

__device__ __forceinline__ float selu_f(float x) {
    const float alpha = 1.6732632423543772f;
    const float scale = 1.0507009873554805f;
    return x > 0.f ? scale * x : scale * alpha * expm1f(x);
}

__device__ __forceinline__ void split1(__nv_bfloat16* db, __nv_bfloat16* ds, float v) {
    __nv_bfloat16 hb = __float2bfloat16(v);
    *db = hb;
    *ds = __float2bfloat16(v - __bfloat162float(hb));
}

__device__ __forceinline__ void split4(__nv_bfloat16* db, __nv_bfloat16* ds, float4 v) {
    split1(db + 0, ds + 0, v.x);
    split1(db + 1, ds + 1, v.y);
    split1(db + 2, ds + 2, v.z);
    split1(db + 3, ds + 3, v.w);
}

// ---------------------------------------------------------------------------
// One dense layer on tensor cores. 256 threads = 8 warps. ROWS fixed at 128:
// warp w owns row strip [16w, 16w+16) and keeps all COLS/16 accumulator
// pairs in registers, so A fragments load once per k-step (not per column
// tile). A: [128 x KDIM] bf16 split pair, W: [KDIM x COLS] bf16 split pair.
// Stages fp32 pre-activations in sF [128 x COLS], applies bias+SELU.
// If LAST, leaves fp32 result in sF; else writes bf16 split pair sOb/sOs.
// Ends synced.
// ---------------------------------------------------------------------------
template<int COLS, int KDIM, bool LAST>
__device__ __forceinline__ void wmma_layer(
    const __nv_bfloat16* __restrict__ sAb, const __nv_bfloat16* __restrict__ sAs,
    const __nv_bfloat16* __restrict__ sWb, const __nv_bfloat16* __restrict__ sWs,
    const float* __restrict__ sBias,
    float* __restrict__ sF,
    __nv_bfloat16* __restrict__ sOb, __nv_bfloat16* __restrict__ sOs,
    const int tid)
{
    constexpr int TILES_N = COLS / 16;
    const int tm = tid >> 5;   // warp id = row strip

    wmma::fragment<wmma::accumulator, 16, 16, 16, float> c1[TILES_N], c2[TILES_N];
    #pragma unroll
    for (int tn = 0; tn < TILES_N; tn++) {
        wmma::fill_fragment(c1[tn], 0.0f);
        wmma::fill_fragment(c2[tn], 0.0f);
    }

    #pragma unroll
    for (int k = 0; k < KDIM; k += 16) {
        wmma::fragment<wmma::matrix_a, 16, 16, 16, __nv_bfloat16, wmma::row_major> ab, as;
        wmma::load_matrix_sync(ab, sAb + tm * 16 * KDIM + k, KDIM);
        wmma::load_matrix_sync(as, sAs + tm * 16 * KDIM + k, KDIM);
        #pragma unroll
        for (int tn = 0; tn < TILES_N; tn++) {
            wmma::fragment<wmma::matrix_b, 16, 16, 16, __nv_bfloat16, wmma::row_major> bb, bs;
            wmma::load_matrix_sync(bb, sWb + k * COLS + tn * 16, COLS);
            wmma::load_matrix_sync(bs, sWs + k * COLS + tn * 16, COLS);
            wmma::mma_sync(c1[tn], ab, bb, c1[tn]);   // hi*hi
            wmma::mma_sync(c2[tn], ab, bs, c2[tn]);   // hi*lo
            wmma::mma_sync(c2[tn], as, bb, c2[tn]);   // lo*hi
        }
    }
    #pragma unroll
    for (int tn = 0; tn < TILES_N; tn++) {
        #pragma unroll
        for (int e = 0; e < c1[tn].num_elements; e++) c1[tn].x[e] += c2[tn].x[e];
        wmma::store_matrix_sync(sF + tm * 16 * COLS + tn * 16, c1[tn], COLS, wmma::mem_row_major);
    }
    __syncthreads();

    for (int i = tid; i < 128 * COLS; i += 256) {
        const int col = i % COLS;   // COLS is a power of two
        const float h = selu_f(sF[i] + sBias[col]);
        if (LAST) {
            sF[i] = h;
        } else {
            split1(sOb + i, sOs + i, h);
        }
    }
    __syncthreads();
}

// ---------------------------------------------------------------------------
// Parallel column-sum of sF [128 x 32] over nvalid rows -> atomicAdd into
// g_sum[32]. All 8 warps participate (16-row strips), staged through sPart
// [8 x 32]. Ends synced (via caller loop-top sync or trailing barrier).
// ---------------------------------------------------------------------------
__device__ __forceinline__ void colsum32(
    const float* __restrict__ sF, float* __restrict__ sPart,
    float* __restrict__ g_sum, const int nvalid, const int tid)
{
    const int col = tid & 31;
    const int grp = tid >> 5;          // 8 groups x 16 rows
    const int rbeg = grp * 16;
    const int rend = min(rbeg + 16, nvalid);
    float s = 0.f;
    for (int e = rbeg; e < rend; e++) s += sF[e * 32 + col];
    sPart[grp * 32 + col] = s;
    __syncthreads();
    if (tid < 32) {
        float t = 0.f;
        #pragma unroll
        for (int g = 0; g < 8; g++) t += sPart[g * 32 + tid];
        atomicAdd(&g_sum[tid], t);
    }
}

// ---------------------------------------------------------------------------
// phi_e smem layout (bytes). Total 191104 (~186.6 KB).
// ---------------------------------------------------------------------------
#define E_OFF_F    0          // fp32 staging 128x64            (32768 B)
#define E_OFF_B1   32768      // bias1 fp32 64                  (256 B)
#define E_OFF_B2   33024      // bias2 fp32 64                  (256 B)
#define E_OFF_B3   33280      // bias3 fp32 32                  (128 B)
#define E_OFF_I1   33408      // ba1 int 128                    (512 B)
#define E_OFF_I2   33920      // ba2 int 128                    (512 B)
#define E_OFF_WB1  34432      // w1 hi bf16 128x64              (16384 B)
#define E_OFF_WS1  50816      // w1 lo
#define E_OFF_WB2  67200      // w2 hi bf16 64x64               (8192 B)
#define E_OFF_WS2  75392
#define E_OFF_WB3  83584      // w3 hi bf16 64x32               (4096 B)
#define E_OFF_WS3  87680
#define E_OFF_XB   91776      // X hi bf16 128x128              (32768 B)
#define E_OFF_XS   124544
#define E_OFF_HB   157312     // H hi bf16 128x64               (16384 B)
#define E_OFF_HS   173696
#define E_OFF_PART 190080     // colsum staging fp32 8x32       (1024 B)
#define E_SMEM_BYTES 191104

__global__ void __launch_bounds__(256, 1) phi_e_kernel(
    const float* __restrict__ bonds,
    const int* __restrict__ ba1, const int* __restrict__ ba2,
    const float* __restrict__ atoms, const float* __restrict__ state,
    const float* __restrict__ w1, const float* __restrict__ b1,
    const float* __restrict__ w2, const float* __restrict__ b2,
    const float* __restrict__ w3, const float* __restrict__ b3,
    float* __restrict__ out_bonds, int E)
{
    extern __shared__ __align__(16) char smraw[];
    float* sF  = reinterpret_cast<float*>(smraw + E_OFF_F);
    float* sB1 = reinterpret_cast<float*>(smraw + E_OFF_B1);
    float* sB2 = reinterpret_cast<float*>(smraw + E_OFF_B2);
    float* sB3 = reinterpret_cast<float*>(smraw + E_OFF_B3);
    int*   sI1 = reinterpret_cast<int*>(smraw + E_OFF_I1);
    int*   sI2 = reinterpret_cast<int*>(smraw + E_OFF_I2);
    __nv_bfloat16* sWb1 = reinterpret_cast<__nv_bfloat16*>(smraw + E_OFF_WB1);
    __nv_bfloat16* sWs1 = reinterpret_cast<__nv_bfloat16*>(smraw + E_OFF_WS1);
    __nv_bfloat16* sWb2 = reinterpret_cast<__nv_bfloat16*>(smraw + E_OFF_WB2);
    __nv_bfloat16* sWs2 = reinterpret_cast<__nv_bfloat16*>(smraw + E_OFF_WS2);
    __nv_bfloat16* sWb3 = reinterpret_cast<__nv_bfloat16*>(smraw + E_OFF_WB3);
    __nv_bfloat16* sWs3 = reinterpret_cast<__nv_bfloat16*>(smraw + E_OFF_WS3);
    __nv_bfloat16* sXb  = reinterpret_cast<__nv_bfloat16*>(smraw + E_OFF_XB);
    __nv_bfloat16* sXs  = reinterpret_cast<__nv_bfloat16*>(smraw + E_OFF_XS);
    __nv_bfloat16* sHb  = reinterpret_cast<__nv_bfloat16*>(smraw + E_OFF_HB);
    __nv_bfloat16* sHs  = reinterpret_cast<__nv_bfloat16*>(smraw + E_OFF_HS);
    float* sPart = reinterpret_cast<float*>(smraw + E_OFF_PART);

    const int tid = threadIdx.x;

    // weights -> smem split pairs, once per CTA
    for (int i = tid; i < 8192; i += 256) split1(sWb1 + i, sWs1 + i, w1[i]);
    for (int i = tid; i < 4096; i += 256) split1(sWb2 + i, sWs2 + i, w2[i]);
    for (int i = tid; i < 2048; i += 256) split1(sWb3 + i, sWs3 + i, w3[i]);
    if (tid < 64) { sB1[tid] = b1[tid]; sB2[tid] = b2[tid]; }
    if (tid < 32) sB3[tid] = b3[tid];

    const float4* atoms4 = reinterpret_cast<const float4*>(atoms);
    const float4* bonds4 = reinterpret_cast<const float4*>(bonds);
    const float4* state4 = reinterpret_cast<const float4*>(state);
    const float4 zero4 = make_float4(0.f, 0.f, 0.f, 0.f);

    const int numTiles = (E + 127) / 128;
    for (int tile = blockIdx.x; tile < numTiles; tile += gridDim.x) {
        const int e0 = tile * 128;
        const int nvalid = min(128, E - e0);

        __syncthreads();   // previous iteration's reads of sF/sI/sPart done
        if (tid < 128) {
            sI1[tid] = (tid < nvalid) ? ba1[e0 + tid] : 0;
            sI2[tid] = (tid < nvalid) ? ba2[e0 + tid] : 0;
        }
        __syncthreads();

        // assemble X = [a1 | a2 | bond | state], 128 rows x 128 cols, split bf16
        for (int i = tid; i < 128 * 8; i += 256) {
            const int e = i >> 3, c = i & 7;
            float4 v1 = zero4, v2 = zero4, vb = zero4, vs = zero4;
            if (e < nvalid) {
                v1 = atoms4[(size_t)sI1[e] * 8 + c];
                v2 = atoms4[(size_t)sI2[e] * 8 + c];
                vb = bonds4[(size_t)(e0 + e) * 8 + c];
                vs = state4[c];
            }
            const int r = e * 128 + c * 4;
            split4(sXb + r,       sXs + r,       v1);
            split4(sXb + r + 32,  sXs + r + 32,  v2);
            split4(sXb + r + 64,  sXs + r + 64,  vb);
            split4(sXb + r + 96,  sXs + r + 96,  vs);
        }
        __syncthreads();

        wmma_layer<64, 128, false>(sXb, sXs, sWb1, sWs1, sB1, sF, sHb, sHs, tid);
        wmma_layer<64,  64, false>(sHb, sHs, sWb2, sWs2, sB2, sF, sXb, sXs, tid);
        wmma_layer<32,  64, true >(sXb, sXs, sWb3, sWs3, sB3, sF, nullptr, nullptr, tid);
        // final fp32 result in sF [128 x 32]

        // write bonds_new
        float4* outb4 = reinterpret_cast<float4*>(out_bonds + (size_t)e0 * 32);
        const float4* sF4 = reinterpret_cast<const float4*>(sF);
        for (int i = tid; i < nvalid * 8; i += 256) outb4[i] = sF4[i];

        // scatter-add bond messages to atom accumulator
        for (int i = tid; i < nvalid * 32; i += 256) {
            const int e = i >> 5;
            atomicAdd(&g_b2a[(size_t)sI1[e] * 32 + (i & 31)], sF[i]);
        }
        if (tid < nvalid) atomicAdd(&g_cnt[sI1[tid]], 1.0f);

        // bond-mean partial: parallel column sums over all 8 warps
        colsum32(sF, sPart, g_bond_sum, nvalid, tid);
    }
}

// ---------------------------------------------------------------------------
// phi_v smem layout (bytes). Total 165504 (~161.6 KB).
// ---------------------------------------------------------------------------
#define V_OFF_F    0          // fp32 staging 128x64            (32768 B)
#define V_OFF_B1   32768
#define V_OFF_B2   33024
#define V_OFF_B3   33280
#define V_OFF_WB1  33408      // w1 hi bf16 96x64               (12288 B)
#define V_OFF_WS1  45696
#define V_OFF_WB2  57984      // w2 hi bf16 64x64               (8192 B)
#define V_OFF_WS2  66176
#define V_OFF_WB3  74368      // w3 hi bf16 64x32               (4096 B)
#define V_OFF_WS3  78464
#define V_OFF_XB   82560      // X hi bf16 128x96               (24576 B)
#define V_OFF_XS   107136
#define V_OFF_HB   131712     // H hi bf16 128x64               (16384 B)
#define V_OFF_HS   148096
#define V_OFF_PART 164480     // colsum staging fp32 8x32       (1024 B)
#define V_SMEM_BYTES 165504

__global__ void __launch_bounds__(256, 1) phi_v_kernel(
    const float* __restrict__ atoms, const float* __restrict__ state,
    const float* __restrict__ w1, const float* __restrict__ b1,
    const float* __restrict__ w2, const float* __restrict__ b2,
    const float* __restrict__ w3, const float* __restrict__ b3,
    float* __restrict__ out_atoms, int N)
{
    extern __shared__ __align__(16) char smraw[];
    float* sF  = reinterpret_cast<float*>(smraw + V_OFF_F);
    float* sB1 = reinterpret_cast<float*>(smraw + V_OFF_B1);
    float* sB2 = reinterpret_cast<float*>(smraw + V_OFF_B2);
    float* sB3 = reinterpret_cast<float*>(smraw + V_OFF_B3);
    __nv_bfloat16* sWb1 = reinterpret_cast<__nv_bfloat16*>(smraw + V_OFF_WB1);
    __nv_bfloat16* sWs1 = reinterpret_cast<__nv_bfloat16*>(smraw + V_OFF_WS1);
    __nv_bfloat16* sWb2 = reinterpret_cast<__nv_bfloat16*>(smraw + V_OFF_WB2);
    __nv_bfloat16* sWs2 = reinterpret_cast<__nv_bfloat16*>(smraw + V_OFF_WS2);
    __nv_bfloat16* sWb3 = reinterpret_cast<__nv_bfloat16*>(smraw + V_OFF_WB3);
    __nv_bfloat16* sWs3 = reinterpret_cast<__nv_bfloat16*>(smraw + V_OFF_WS3);
    __nv_bfloat16* sXb  = reinterpret_cast<__nv_bfloat16*>(smraw + V_OFF_XB);
    __nv_bfloat16* sXs  = reinterpret_cast<__nv_bfloat16*>(smraw + V_OFF_XS);
    __nv_bfloat16* sHb  = reinterpret_cast<__nv_bfloat16*>(smraw + V_OFF_HB);
    __nv_bfloat16* sHs  = reinterpret_cast<__nv_bfloat16*>(smraw + V_OFF_HS);
    float* sPart = reinterpret_cast<float*>(smraw + V_OFF_PART);

    const int tid = threadIdx.x;

    for (int i = tid; i < 6144; i += 256) split1(sWb1 + i, sWs1 + i, w1[i]);
    for (int i = tid; i < 4096; i += 256) split1(sWb2 + i, sWs2 + i, w2[i]);
    for (int i = tid; i < 2048; i += 256) split1(sWb3 + i, sWs3 + i, w3[i]);
    if (tid < 64) { sB1[tid] = b1[tid]; sB2[tid] = b2[tid]; }
    if (tid < 32) sB3[tid] = b3[tid];

    const float4* atoms4 = reinterpret_cast<const float4*>(atoms);
    const float4* state4 = reinterpret_cast<const float4*>(state);
    const float4* b2a4   = reinterpret_cast<const float4*>(g_b2a);

    const int numTiles = (N + 127) / 128;
    for (int tile = blockIdx.x; tile < numTiles; tile += gridDim.x) {
        const int a0 = tile * 128;
        const int nvalid = min(128, N - a0);

        __syncthreads();

        // assemble X = [b2a/cnt | atom | state], 128 rows x 96 cols, split bf16
        for (int i = tid; i < 128 * 24; i += 256) {
            const int e = i / 24, c = i % 24;
            const int a = a0 + e;
            float4 v = make_float4(0.f, 0.f, 0.f, 0.f);
            if (a < N) {
                if (c < 8) {
                    const float inv = 1.0f / g_cnt[a];
                    float4 t = b2a4[(size_t)a * 8 + c];
                    v = make_float4(t.x * inv, t.y * inv, t.z * inv, t.w * inv);
                } else if (c < 16) {
                    v = atoms4[(size_t)a * 8 + (c - 8)];
                } else {
                    v = state4[c - 16];
                }
            }
            const int r = e * 96 + c * 4;
            split4(sXb + r, sXs + r, v);
        }
        __syncthreads();

        wmma_layer<64, 96, false>(sXb, sXs, sWb1, sWs1, sB1, sF, sHb, sHs, tid);
        wmma_layer<64, 64, false>(sHb, sHs, sWb2, sWs2, sB2, sF, sXb, sXs, tid);
        wmma_layer<32, 64, true >(sXb, sXs, sWb3, sWs3, sB3, sF, nullptr, nullptr, tid);

        float4* outa4 = reinterpret_cast<float4*>(out_atoms + (size_t)a0 * 32);
        const float4* sF4 = reinterpret_cast<const float4*>(sF);
        for (int i = tid; i < nvalid * 8; i += 256) outa4[i] = sF4[i];

        // atom-mean partial: parallel column sums over all 8 warps
        colsum32(sF, sPart, g_atom_sum, nvalid, tid);
    }
}

// ---------------------------------------------------------------------------
// phi_u: state MLP 96 -> 64 -> 64 -> 32 (single block, fp32).
// ---------------------------------------------------------------------------
__global__ void phi_u_kernel(
    const float* __restrict__ state,
    const float* __restrict__ w1, const float* __restrict__ b1,
    const float* __restrict__ w2, const float* __restrict__ b2,
    const float* __restrict__ w3, const float* __restrict__ b3,
    float* __restrict__ out_state, int E, int N)
{
    __shared__ float x[96], h1[64], h2[64];
    const int t = threadIdx.x;
    if (t < 32) {
        x[t]      = g_bond_sum[t] / (float)E;
        x[32 + t] = g_atom_sum[t] / (float)N;
        x[64 + t] = state[t];
    }
    __syncthreads();
    if (t < 64) {
        float s = b1[t];
        for (int k = 0; k < 96; k++) s = fmaf(x[k], w1[k * 64 + t], s);
        h1[t] = selu_f(s);
    }
    __syncthreads();
    if (t < 64) {
        float s = b2[t];
        for (int k = 0; k < 64; k++) s = fmaf(h1[k], w2[k * 64 + t], s);
        h2[t] = selu_f(s);
    }
    __syncthreads();
    if (t < 32) {
        float s = b3[t];
        for (int k = 0; k < 64; k++) s = fmaf(h2[k], w3[k * 32 + t], s);
        out_state[t] = selu_f(s);
    }
}

__global__ void zero_scratch_kernel(int N)
{
    const int i = blockIdx.x * blockDim.x + threadIdx.x;
    const int nb4 = N * 8;   // N*32 floats as float4
    float4* b2a4 = reinterpret_cast<float4*>(g_b2a);
    const float4 z4 = make_float4(0.f, 0.f, 0.f, 0.f);
    if (i < nb4) b2a4[i] = z4;
    if (i < N)  g_cnt[i] = 0.f;
    if (i < 32) { g_bond_sum[i] = 0.f; g_atom_sum[i] = 0.f; }
}

// ---------------------------------------------------------------------------

extern "C" void kernel_launch(void* const* d_in, const int* in_sizes, int n_in,
                              void* d_out, int out_size)
{
    const float* bonds = (const float*)d_in[0];
    const int*   ba1   = (const int*)d_in[1];
    const int*   ba2   = (const int*)d_in[2];
    const float* atoms = (const float*)d_in[3];
    const float* state = (const float*)d_in[4];
    const float* e_w1 = (const float*)d_in[5],  *e_b1 = (const float*)d_in[6];
    const float* e_w2 = (const float*)d_in[7],  *e_b2 = (const float*)d_in[8];
    const float* e_w3 = (const float*)d_in[9],  *e_b3 = (const float*)d_in[10];
    const float* v_w1 = (const float*)d_in[11], *v_b1 = (const float*)d_in[12];
    const float* v_w2 = (const float*)d_in[13], *v_b2 = (const float*)d_in[14];
    const float* v_w3 = (const float*)d_in[15], *v_b3 = (const float*)d_in[16];
    const float* u_w1 = (const float*)d_in[17], *u_b1 = (const float*)d_in[18];
    const float* u_w2 = (const float*)d_in[19], *u_b2 = (const float*)d_in[20];
    const float* u_w3 = (const float*)d_in[21], *u_b3 = (const float*)d_in[22];

    const int E = in_sizes[1];
    const int N = in_sizes[3] / 32;

    float* out_bonds = (float*)d_out;
    float* out_atoms = out_bonds + (size_t)E * 32;
    float* out_state = out_atoms + (size_t)N * 32;

    cudaFuncSetAttribute(phi_e_kernel, cudaFuncAttributeMaxDynamicSharedMemorySize, E_SMEM_BYTES);
    cudaFuncSetAttribute(phi_v_kernel, cudaFuncAttributeMaxDynamicSharedMemorySize, V_SMEM_BYTES);

    const int numTilesE = (E + 127) / 128;
    const int numTilesV = (N + 127) / 128;
    const int gridE = numTilesE < PERSISTENT_GRID ? numTilesE : PERSISTENT_GRID;
    const int gridV = numTilesV < PERSISTENT_GRID ? numTilesV : PERSISTENT_GRID;

    zero_scratch_kernel<<<(N * 8 + 255) / 256, 256>>>(N);
    phi_e_kernel<<<gridE, 256, E_SMEM_BYTES>>>(
        bonds, ba1, ba2, atoms, state,
        e_w1, e_b1, e_w2, e_b2, e_w3, e_b3, out_bonds, E);
    phi_v_kernel<<<gridV, 256, V_SMEM_BYTES>>>(
        atoms, state, v_w1, v_b1, v_w2, v_b2, v_w3, v_b3, out_atoms, N);
    phi_u_kernel<<<1, 96>>>(
        state, u_w1, u_b1, u_w2, u_b2, u_w3, u_b3, out_state, E, N);
}

// round 8
// speedup vs baseline: 1.7470x; 1.7470x over previous
#include <cuda_runtime.h>
#include <cuda_bf16.h>
#include <mma.h>
#include <math.h>

using namespace nvcuda;

// ---------------------------------------------------------------------------
// MegNet layer. Tensor-core (bf16 split, fp32 accum) persistent-CTA version.
// Padded smem strides (kill 8-way LDSM bank conflicts) + v4 red scatter.
// Inputs (metadata order):
//  0 bonds[E,32] f32, 1 bond_atom_1[E] i32, 2 bond_atom_2[E] i32,
//  3 atoms[N,32] f32, 4 state[1,32] f32,
//  5..10  e_w1[128,64] e_b1[64] e_w2[64,64] e_b2[64] e_w3[64,32] e_b3[32]
// 11..16  v_w1[96,64]  v_b1     v_w2        v_b2     v_w3        v_b3
// 17..22  u_w1[96,64]  u_b1     u_w2        u_b2     u_w3        u_b3
// Output: concat(bonds_new[E,32], atoms_new[N,32], state_new[1,32]) f32
// ---------------------------------------------------------------------------

#define MAXN 100000
#define PERSISTENT_GRID 152

__device__ __align__(16) float g_b2a[(size_t)MAXN * 32];
__device__ float g_cnt[MAXN];
__device__ float g_bond_sum[32];
__device__ float g_atom_sum[32];

__device__ __forceinline__ float selu_f(float x) {
    const float alpha = 1.6732632423543772f;
    const float scale = 1.0507009873554805f;
    return x > 0.f ? scale * x : scale * alpha * expm1f(x);
}

__device__ __forceinline__ void split1(__nv_bfloat16* db, __nv_bfloat16* ds, float v) {
    __nv_bfloat16 hb = __float2bfloat16(v);
    *db = hb;
    *ds = __float2bfloat16(v - __bfloat162float(hb));
}

__device__ __forceinline__ void split4(__nv_bfloat16* db, __nv_bfloat16* ds, float4 v) {
    split1(db + 0, ds + 0, v.x);
    split1(db + 1, ds + 1, v.y);
    split1(db + 2, ds + 2, v.z);
    split1(db + 3, ds + 3, v.w);
}

__device__ __forceinline__ void red_add_v4(float* gptr, float4 v) {
    asm volatile("red.global.add.v4.f32 [%0], {%1, %2, %3, %4};"
                 :: "l"(gptr), "f"(v.x), "f"(v.y), "f"(v.z), "f"(v.w) : "memory");
}

// ---------------------------------------------------------------------------
// One dense layer on tensor cores. 256 threads = 8 warps; warp w owns row
// strip [16w, 16w+16) of the fixed 128-row tile and holds all COLS/16
// accumulator pairs in registers. All smem strides (LDA/LDW/FS/LDO) are
// padded off powers of two for conflict-free LDSM/LDS.
// Numerics: A = Ab + As, W = Wb + Ws (bf16 split); D = Ab*Wb + Ab*Ws + As*Wb.
// Stages fp32 pre-activations in sF (stride FS), applies bias+SELU.
// If LAST, leaves fp32 result in sF; else writes split pair sOb/sOs (stride LDO).
// ---------------------------------------------------------------------------
template<int COLS, int KDIM, int LDA, int LDW, int FS, int LDO, bool LAST>
__device__ __forceinline__ void wmma_layer(
    const __nv_bfloat16* __restrict__ sAb, const __nv_bfloat16* __restrict__ sAs,
    const __nv_bfloat16* __restrict__ sWb, const __nv_bfloat16* __restrict__ sWs,
    const float* __restrict__ sBias,
    float* __restrict__ sF,
    __nv_bfloat16* __restrict__ sOb, __nv_bfloat16* __restrict__ sOs,
    const int tid)
{
    constexpr int TILES_N = COLS / 16;
    const int tm = tid >> 5;   // warp id = row strip

    wmma::fragment<wmma::accumulator, 16, 16, 16, float> c1[TILES_N], c2[TILES_N];
    #pragma unroll
    for (int tn = 0; tn < TILES_N; tn++) {
        wmma::fill_fragment(c1[tn], 0.0f);
        wmma::fill_fragment(c2[tn], 0.0f);
    }

    #pragma unroll
    for (int k = 0; k < KDIM; k += 16) {
        wmma::fragment<wmma::matrix_a, 16, 16, 16, __nv_bfloat16, wmma::row_major> ab, as;
        wmma::load_matrix_sync(ab, sAb + tm * 16 * LDA + k, LDA);
        wmma::load_matrix_sync(as, sAs + tm * 16 * LDA + k, LDA);
        #pragma unroll
        for (int tn = 0; tn < TILES_N; tn++) {
            wmma::fragment<wmma::matrix_b, 16, 16, 16, __nv_bfloat16, wmma::row_major> bb, bs;
            wmma::load_matrix_sync(bb, sWb + k * LDW + tn * 16, LDW);
            wmma::load_matrix_sync(bs, sWs + k * LDW + tn * 16, LDW);
            wmma::mma_sync(c1[tn], ab, bb, c1[tn]);   // hi*hi
            wmma::mma_sync(c2[tn], ab, bs, c2[tn]);   // hi*lo
            wmma::mma_sync(c2[tn], as, bb, c2[tn]);   // lo*hi
        }
    }
    #pragma unroll
    for (int tn = 0; tn < TILES_N; tn++) {
        #pragma unroll
        for (int e = 0; e < c1[tn].num_elements; e++) c1[tn].x[e] += c2[tn].x[e];
        wmma::store_matrix_sync(sF + tm * 16 * FS + tn * 16, c1[tn], FS, wmma::mem_row_major);
    }
    __syncthreads();

    for (int i = tid; i < 128 * COLS; i += 256) {
        const int row = i / COLS;          // COLS is a power of two
        const int col = i & (COLS - 1);
        const float h = selu_f(sF[row * FS + col] + sBias[col]);
        if (LAST) {
            sF[row * FS + col] = h;
        } else {
            split1(sOb + row * LDO + col, sOs + row * LDO + col, h);
        }
    }
    __syncthreads();
}

// ---------------------------------------------------------------------------
// Parallel column-sum of sF [128 x 32, stride 36] over nvalid rows ->
// atomicAdd into g_sum[32]. 8 warps x 16-row strips staged through sPart.
// ---------------------------------------------------------------------------
__device__ __forceinline__ void colsum32(
    const float* __restrict__ sF, float* __restrict__ sPart,
    float* __restrict__ g_sum, const int nvalid, const int tid)
{
    const int col = tid & 31;
    const int grp = tid >> 5;
    const int rbeg = grp * 16;
    const int rend = min(rbeg + 16, nvalid);
    float s = 0.f;
    for (int e = rbeg; e < rend; e++) s += sF[e * 36 + col];
    sPart[grp * 32 + col] = s;
    __syncthreads();
    if (tid < 32) {
        float t = 0.f;
        #pragma unroll
        for (int g = 0; g < 8; g++) t += sPart[g * 32 + tid];
        atomicAdd(&g_sum[tid], t);
    }
}

// ---------------------------------------------------------------------------
// phi_e smem layout (bytes). Padded strides: X 136, H/W 72, W3 40, sF 68/36.
// Total 209536 (~204.6 KB).
// ---------------------------------------------------------------------------
#define E_OFF_F    0          // fp32 staging 128x68            (34816 B)
#define E_OFF_B1   34816
#define E_OFF_B2   35072
#define E_OFF_B3   35328
#define E_OFF_I1   35456
#define E_OFF_I2   35968
#define E_OFF_WB1  36480      // w1 hi bf16 128x72              (18432 B)
#define E_OFF_WS1  54912
#define E_OFF_WB2  73344      // w2 hi bf16 64x72               (9216 B)
#define E_OFF_WS2  82560
#define E_OFF_WB3  91776      // w3 hi bf16 64x40               (5120 B)
#define E_OFF_WS3  96896
#define E_OFF_XB   102016     // X hi bf16 128x136              (34816 B)
#define E_OFF_XS   136832
#define E_OFF_HB   171648     // H hi bf16 128x72               (18432 B)
#define E_OFF_HS   190080
#define E_OFF_PART 208512     // colsum staging fp32 8x32       (1024 B)
#define E_SMEM_BYTES 209536

__global__ void __launch_bounds__(256, 1) phi_e_kernel(
    const float* __restrict__ bonds,
    const int* __restrict__ ba1, const int* __restrict__ ba2,
    const float* __restrict__ atoms, const float* __restrict__ state,
    const float* __restrict__ w1, const float* __restrict__ b1,
    const float* __restrict__ w2, const float* __restrict__ b2,
    const float* __restrict__ w3, const float* __restrict__ b3,
    float* __restrict__ out_bonds, int E)
{
    extern __shared__ __align__(16) char smraw[];
    float* sF  = reinterpret_cast<float*>(smraw + E_OFF_F);
    float* sB1 = reinterpret_cast<float*>(smraw + E_OFF_B1);
    float* sB2 = reinterpret_cast<float*>(smraw + E_OFF_B2);
    float* sB3 = reinterpret_cast<float*>(smraw + E_OFF_B3);
    int*   sI1 = reinterpret_cast<int*>(smraw + E_OFF_I1);
    int*   sI2 = reinterpret_cast<int*>(smraw + E_OFF_I2);
    __nv_bfloat16* sWb1 = reinterpret_cast<__nv_bfloat16*>(smraw + E_OFF_WB1);
    __nv_bfloat16* sWs1 = reinterpret_cast<__nv_bfloat16*>(smraw + E_OFF_WS1);
    __nv_bfloat16* sWb2 = reinterpret_cast<__nv_bfloat16*>(smraw + E_OFF_WB2);
    __nv_bfloat16* sWs2 = reinterpret_cast<__nv_bfloat16*>(smraw + E_OFF_WS2);
    __nv_bfloat16* sWb3 = reinterpret_cast<__nv_bfloat16*>(smraw + E_OFF_WB3);
    __nv_bfloat16* sWs3 = reinterpret_cast<__nv_bfloat16*>(smraw + E_OFF_WS3);
    __nv_bfloat16* sXb  = reinterpret_cast<__nv_bfloat16*>(smraw + E_OFF_XB);
    __nv_bfloat16* sXs  = reinterpret_cast<__nv_bfloat16*>(smraw + E_OFF_XS);
    __nv_bfloat16* sHb  = reinterpret_cast<__nv_bfloat16*>(smraw + E_OFF_HB);
    __nv_bfloat16* sHs  = reinterpret_cast<__nv_bfloat16*>(smraw + E_OFF_HS);
    float* sPart = reinterpret_cast<float*>(smraw + E_OFF_PART);

    const int tid = threadIdx.x;

    // weights -> smem split pairs at padded strides, once per CTA
    for (int i = tid; i < 8192; i += 256) {
        const int k = i >> 6, j = i & 63;
        split1(sWb1 + k * 72 + j, sWs1 + k * 72 + j, w1[i]);
    }
    for (int i = tid; i < 4096; i += 256) {
        const int k = i >> 6, j = i & 63;
        split1(sWb2 + k * 72 + j, sWs2 + k * 72 + j, w2[i]);
    }
    for (int i = tid; i < 2048; i += 256) {
        const int k = i >> 5, j = i & 31;
        split1(sWb3 + k * 40 + j, sWs3 + k * 40 + j, w3[i]);
    }
    if (tid < 64) { sB1[tid] = b1[tid]; sB2[tid] = b2[tid]; }
    if (tid < 32) sB3[tid] = b3[tid];

    const float4* atoms4 = reinterpret_cast<const float4*>(atoms);
    const float4* bonds4 = reinterpret_cast<const float4*>(bonds);
    const float4* state4 = reinterpret_cast<const float4*>(state);
    const float4 zero4 = make_float4(0.f, 0.f, 0.f, 0.f);

    const int numTiles = (E + 127) / 128;
    for (int tile = blockIdx.x; tile < numTiles; tile += gridDim.x) {
        const int e0 = tile * 128;
        const int nvalid = min(128, E - e0);

        __syncthreads();   // previous iteration's reads of sF/sI/sPart done
        if (tid < 128) {
            sI1[tid] = (tid < nvalid) ? ba1[e0 + tid] : 0;
            sI2[tid] = (tid < nvalid) ? ba2[e0 + tid] : 0;
        }
        __syncthreads();

        // assemble X = [a1 | a2 | bond | state], 128 rows x 128 cols (stride 136)
        for (int i = tid; i < 128 * 8; i += 256) {
            const int e = i >> 3, c = i & 7;
            float4 v1 = zero4, v2 = zero4, vb = zero4, vs = zero4;
            if (e < nvalid) {
                v1 = atoms4[(size_t)sI1[e] * 8 + c];
                v2 = atoms4[(size_t)sI2[e] * 8 + c];
                vb = bonds4[(size_t)(e0 + e) * 8 + c];
                vs = state4[c];
            }
            const int r = e * 136 + c * 4;
            split4(sXb + r,       sXs + r,       v1);
            split4(sXb + r + 32,  sXs + r + 32,  v2);
            split4(sXb + r + 64,  sXs + r + 64,  vb);
            split4(sXb + r + 96,  sXs + r + 96,  vs);
        }
        __syncthreads();

        wmma_layer<64, 128, 136, 72, 68, 72, false>(sXb, sXs, sWb1, sWs1, sB1, sF, sHb, sHs, tid);
        wmma_layer<64,  64,  72, 72, 68, 72, false>(sHb, sHs, sWb2, sWs2, sB2, sF, sXb, sXs, tid);
        wmma_layer<32,  64,  72, 40, 36,  0, true >(sXb, sXs, sWb3, sWs3, sB3, sF, nullptr, nullptr, tid);
        // final fp32 result in sF [128 x 32, stride 36]

        // write bonds_new + vector-scatter to atom accumulator
        for (int i = tid; i < nvalid * 8; i += 256) {
            const int e = i >> 3, c = (i & 7) * 4;
            const float4 v = *reinterpret_cast<const float4*>(sF + e * 36 + c);
            *reinterpret_cast<float4*>(out_bonds + (size_t)(e0 + e) * 32 + c) = v;
            red_add_v4(&g_b2a[(size_t)sI1[e] * 32 + c], v);
        }
        if (tid < nvalid) atomicAdd(&g_cnt[sI1[tid]], 1.0f);

        // bond-mean partial: parallel column sums over all 8 warps
        colsum32(sF, sPart, g_bond_sum, nvalid, tid);
    }
}

// ---------------------------------------------------------------------------
// phi_v smem layout (bytes). X stride 104, H/W 72, W3 40, sF 68/36.
// Total 182912 (~178.6 KB).
// ---------------------------------------------------------------------------
#define V_OFF_F    0          // fp32 staging 128x68            (34816 B)
#define V_OFF_B1   34816
#define V_OFF_B2   35072
#define V_OFF_B3   35328
#define V_OFF_WB1  35456      // w1 hi bf16 96x72               (13824 B)
#define V_OFF_WS1  49280
#define V_OFF_WB2  63104      // w2 hi bf16 64x72               (9216 B)
#define V_OFF_WS2  72320
#define V_OFF_WB3  81536      // w3 hi bf16 64x40               (5120 B)
#define V_OFF_WS3  86656
#define V_OFF_XB   91776      // X hi bf16 128x104              (26624 B)
#define V_OFF_XS   118400
#define V_OFF_HB   145024     // H hi bf16 128x72               (18432 B)
#define V_OFF_HS   163456
#define V_OFF_PART 181888     // colsum staging fp32 8x32       (1024 B)
#define V_SMEM_BYTES 182912

__global__ void __launch_bounds__(256, 1) phi_v_kernel(
    const float* __restrict__ atoms, const float* __restrict__ state,
    const float* __restrict__ w1, const float* __restrict__ b1,
    const float* __restrict__ w2, const float* __restrict__ b2,
    const float* __restrict__ w3, const float* __restrict__ b3,
    float* __restrict__ out_atoms, int N)
{
    extern __shared__ __align__(16) char smraw[];
    float* sF  = reinterpret_cast<float*>(smraw + V_OFF_F);
    float* sB1 = reinterpret_cast<float*>(smraw + V_OFF_B1);
    float* sB2 = reinterpret_cast<float*>(smraw + V_OFF_B2);
    float* sB3 = reinterpret_cast<float*>(smraw + V_OFF_B3);
    __nv_bfloat16* sWb1 = reinterpret_cast<__nv_bfloat16*>(smraw + V_OFF_WB1);
    __nv_bfloat16* sWs1 = reinterpret_cast<__nv_bfloat16*>(smraw + V_OFF_WS1);
    __nv_bfloat16* sWb2 = reinterpret_cast<__nv_bfloat16*>(smraw + V_OFF_WB2);
    __nv_bfloat16* sWs2 = reinterpret_cast<__nv_bfloat16*>(smraw + V_OFF_WS2);
    __nv_bfloat16* sWb3 = reinterpret_cast<__nv_bfloat16*>(smraw + V_OFF_WB3);
    __nv_bfloat16* sWs3 = reinterpret_cast<__nv_bfloat16*>(smraw + V_OFF_WS3);
    __nv_bfloat16* sXb  = reinterpret_cast<__nv_bfloat16*>(smraw + V_OFF_XB);
    __nv_bfloat16* sXs  = reinterpret_cast<__nv_bfloat16*>(smraw + V_OFF_XS);
    __nv_bfloat16* sHb  = reinterpret_cast<__nv_bfloat16*>(smraw + V_OFF_HB);
    __nv_bfloat16* sHs  = reinterpret_cast<__nv_bfloat16*>(smraw + V_OFF_HS);
    float* sPart = reinterpret_cast<float*>(smraw + V_OFF_PART);

    const int tid = threadIdx.x;

    for (int i = tid; i < 6144; i += 256) {
        const int k = i >> 6, j = i & 63;
        split1(sWb1 + k * 72 + j, sWs1 + k * 72 + j, w1[i]);
    }
    for (int i = tid; i < 4096; i += 256) {
        const int k = i >> 6, j = i & 63;
        split1(sWb2 + k * 72 + j, sWs2 + k * 72 + j, w2[i]);
    }
    for (int i = tid; i < 2048; i += 256) {
        const int k = i >> 5, j = i & 31;
        split1(sWb3 + k * 40 + j, sWs3 + k * 40 + j, w3[i]);
    }
    if (tid < 64) { sB1[tid] = b1[tid]; sB2[tid] = b2[tid]; }
    if (tid < 32) sB3[tid] = b3[tid];

    const float4* atoms4 = reinterpret_cast<const float4*>(atoms);
    const float4* state4 = reinterpret_cast<const float4*>(state);
    const float4* b2a4   = reinterpret_cast<const float4*>(g_b2a);

    const int numTiles = (N + 127) / 128;
    for (int tile = blockIdx.x; tile < numTiles; tile += gridDim.x) {
        const int a0 = tile * 128;
        const int nvalid = min(128, N - a0);

        __syncthreads();

        // assemble X = [b2a/cnt | atom | state], 128 rows x 96 cols (stride 104)
        for (int i = tid; i < 128 * 24; i += 256) {
            const int e = i / 24, c = i % 24;
            const int a = a0 + e;
            float4 v = make_float4(0.f, 0.f, 0.f, 0.f);
            if (a < N) {
                if (c < 8) {
                    const float inv = 1.0f / g_cnt[a];
                    float4 t = b2a4[(size_t)a * 8 + c];
                    v = make_float4(t.x * inv, t.y * inv, t.z * inv, t.w * inv);
                } else if (c < 16) {
                    v = atoms4[(size_t)a * 8 + (c - 8)];
                } else {
                    v = state4[c - 16];
                }
            }
            const int r = e * 104 + c * 4;
            split4(sXb + r, sXs + r, v);
        }
        __syncthreads();

        wmma_layer<64, 96, 104, 72, 68, 72, false>(sXb, sXs, sWb1, sWs1, sB1, sF, sHb, sHs, tid);
        wmma_layer<64, 64,  72, 72, 68, 72, false>(sHb, sHs, sWb2, sWs2, sB2, sF, sXb, sXs, tid);
        wmma_layer<32, 64,  72, 40, 36,  0, true >(sXb, sXs, sWb3, sWs3, sB3, sF, nullptr, nullptr, tid);

        for (int i = tid; i < nvalid * 8; i += 256) {
            const int e = i >> 3, c = (i & 7) * 4;
            const float4 v = *reinterpret_cast<const float4*>(sF + e * 36 + c);
            *reinterpret_cast<float4*>(out_atoms + (size_t)(a0 + e) * 32 + c) = v;
        }

        // atom-mean partial: parallel column sums over all 8 warps
        colsum32(sF, sPart, g_atom_sum, nvalid, tid);
    }
}

// ---------------------------------------------------------------------------
// phi_u: state MLP 96 -> 64 -> 64 -> 32 (single block, fp32).
// ---------------------------------------------------------------------------
__global__ void phi_u_kernel(
    const float* __restrict__ state,
    const float* __restrict__ w1, const float* __restrict__ b1,
    const float* __restrict__ w2, const float* __restrict__ b2,
    const float* __restrict__ w3, const float* __restrict__ b3,
    float* __restrict__ out_state, int E, int N)
{
    __shared__ float x[96], h1[64], h2[64];
    const int t = threadIdx.x;
    if (t < 32) {
        x[t]      = g_bond_sum[t] / (float)E;
        x[32 + t] = g_atom_sum[t] / (float)N;
        x[64 + t] = state[t];
    }
    __syncthreads();
    if (t < 64) {
        float s = b1[t];
        for (int k = 0; k < 96; k++) s = fmaf(x[k], w1[k * 64 + t], s);
        h1[t] = selu_f(s);
    }
    __syncthreads();
    if (t < 64) {
        float s = b2[t];
        for (int k = 0; k < 64; k++) s = fmaf(h1[k], w2[k * 64 + t], s);
        h2[t] = selu_f(s);
    }
    __syncthreads();
    if (t < 32) {
        float s = b3[t];
        for (int k = 0; k < 64; k++) s = fmaf(h2[k], w3[k * 32 + t], s);
        out_state[t] = selu_f(s);
    }
}

__global__ void zero_scratch_kernel(int N)
{
    const int i = blockIdx.x * blockDim.x + threadIdx.x;
    const int nb4 = N * 8;   // N*32 floats as float4
    float4* b2a4 = reinterpret_cast<float4*>(g_b2a);
    const float4 z4 = make_float4(0.f, 0.f, 0.f, 0.f);
    if (i < nb4) b2a4[i] = z4;
    if (i < N)  g_cnt[i] = 0.f;
    if (i < 32) { g_bond_sum[i] = 0.f; g_atom_sum[i] = 0.f; }
}

// ---------------------------------------------------------------------------

extern "C" void kernel_launch(void* const* d_in, const int* in_sizes, int n_in,
                              void* d_out, int out_size)
{
    const float* bonds = (const float*)d_in[0];
    const int*   ba1   = (const int*)d_in[1];
    const int*   ba2   = (const int*)d_in[2];
    const float* atoms = (const float*)d_in[3];
    const float* state = (const float*)d_in[4];
    const float* e_w1 = (const float*)d_in[5],  *e_b1 = (const float*)d_in[6];
    const float* e_w2 = (const float*)d_in[7],  *e_b2 = (const float*)d_in[8];
    const float* e_w3 = (const float*)d_in[9],  *e_b3 = (const float*)d_in[10];
    const float* v_w1 = (const float*)d_in[11], *v_b1 = (const float*)d_in[12];
    const float* v_w2 = (const float*)d_in[13], *v_b2 = (const float*)d_in[14];
    const float* v_w3 = (const float*)d_in[15], *v_b3 = (const float*)d_in[16];
    const float* u_w1 = (const float*)d_in[17], *u_b1 = (const float*)d_in[18];
    const float* u_w2 = (const float*)d_in[19], *u_b2 = (const float*)d_in[20];
    const float* u_w3 = (const float*)d_in[21], *u_b3 = (const float*)d_in[22];

    const int E = in_sizes[1];
    const int N = in_sizes[3] / 32;

    float* out_bonds = (float*)d_out;
    float* out_atoms = out_bonds + (size_t)E * 32;
    float* out_state = out_atoms + (size_t)N * 32;

    cudaFuncSetAttribute(phi_e_kernel, cudaFuncAttributeMaxDynamicSharedMemorySize, E_SMEM_BYTES);
    cudaFuncSetAttribute(phi_v_kernel, cudaFuncAttributeMaxDynamicSharedMemorySize, V_SMEM_BYTES);

    const int numTilesE = (E + 127) / 128;
    const int numTilesV = (N + 127) / 128;
    const int gridE = numTilesE < PERSISTENT_GRID ? numTilesE : PERSISTENT_GRID;
    const int gridV = numTilesV < PERSISTENT_GRID ? numTilesV : PERSISTENT_GRID;

    zero_scratch_kernel<<<(N * 8 + 255) / 256, 256>>>(N);
    phi_e_kernel<<<gridE, 256, E_SMEM_BYTES>>>(
        bonds, ba1, ba2, atoms, state,
        e_w1, e_b1, e_w2, e_b2, e_w3, e_b3, out_bonds, E);
    phi_v_kernel<<<gridV, 256, V_SMEM_BYTES>>>(
        atoms, state, v_w1, v_b1, v_w2, v_b2, v_w3, v_b3, out_atoms, N);
    phi_u_kernel<<<1, 96>>>(
        state, u_w1, u_b1, u_w2, u_b2, u_w3, u_b3, out_state, E, N);
}

// round 14
// speedup vs baseline: 2.4013x; 1.3745x over previous
#include <cuda_runtime.h>
#include <cuda_bf16.h>
#include <math.h>
#include <stdint.h>

// ---------------------------------------------------------------------------
// MegNet layer. Raw mma.sync (bf16 split, fp32 accum), persistent CTAs,
// fully warp-local tile pipeline (no __syncthreads in the tile loop).
// Inputs (metadata order):
//  0 bonds[E,32] f32, 1 bond_atom_1[E] i32, 2 bond_atom_2[E] i32,
//  3 atoms[N,32] f32, 4 state[1,32] f32,
//  5..10  e_w1[128,64] e_b1[64] e_w2[64,64] e_b2[64] e_w3[64,32] e_b3[32]
// 11..16  v_w1[96,64]  v_b1     v_w2        v_b2     v_w3        v_b3
// 17..22  u_w1[96,64]  u_b1     u_w2        u_b2     u_w3        u_b3
// Output: concat(bonds_new[E,32], atoms_new[N,32], state_new[1,32]) f32
//
// Numerics: x = hi + lo (bf16 pair); D = Ab*Wb + Ab*Ws + As*Wb (fp32 accum),
// rel err ~1e-5.
// ---------------------------------------------------------------------------

#define MAXN 100000
#define PERSISTENT_GRID 152

__device__ __align__(16) float g_b2a[(size_t)MAXN * 32];
__device__ float g_cnt[MAXN];
__device__ float g_bond_sum[32];
__device__ float g_atom_sum[32];

__device__ __forceinline__ float selu_f(float x) {
    const float alpha = 1.6732632423543772f;
    const float scale = 1.0507009873554805f;
    return x > 0.f ? scale * x : scale * alpha * expm1f(x);
}

__device__ __forceinline__ void split1(__nv_bfloat16* db, __nv_bfloat16* ds, float v) {
    __nv_bfloat16 hb = __float2bfloat16(v);
    *db = hb;
    *ds = __float2bfloat16(v - __bfloat162float(hb));
}

__device__ __forceinline__ void split4(__nv_bfloat16* db, __nv_bfloat16* ds, float4 v) {
    split1(db + 0, ds + 0, v.x);
    split1(db + 1, ds + 1, v.y);
    split1(db + 2, ds + 2, v.z);
    split1(db + 3, ds + 3, v.w);
}

// pack two fp32 into bf16x2 hi and lo (lo = residual), little-end = v0
__device__ __forceinline__ void split_pair(float v0, float v1, uint32_t& hi, uint32_t& lo) {
    __nv_bfloat162 h = __floats2bfloat162_rn(v0, v1);
    float r0 = v0 - __bfloat162float(h.x);
    float r1 = v1 - __bfloat162float(h.y);
    __nv_bfloat162 l = __floats2bfloat162_rn(r0, r1);
    hi = reinterpret_cast<uint32_t&>(h);
    lo = reinterpret_cast<uint32_t&>(l);
}

__device__ __forceinline__ uint32_t sptr(const void* p) {
    return (uint32_t)__cvta_generic_to_shared(p);
}

__device__ __forceinline__ void ldsm_x4(uint32_t& r0, uint32_t& r1, uint32_t& r2, uint32_t& r3, uint32_t addr) {
    asm volatile("ldmatrix.sync.aligned.m8n8.x4.shared.b16 {%0,%1,%2,%3}, [%4];\n"
                 : "=r"(r0), "=r"(r1), "=r"(r2), "=r"(r3) : "r"(addr));
}

__device__ __forceinline__ void ldsm_x4_t(uint32_t& r0, uint32_t& r1, uint32_t& r2, uint32_t& r3, uint32_t addr) {
    asm volatile("ldmatrix.sync.aligned.m8n8.x4.trans.shared.b16 {%0,%1,%2,%3}, [%4];\n"
                 : "=r"(r0), "=r"(r1), "=r"(r2), "=r"(r3) : "r"(addr));
}

__device__ __forceinline__ void mma16816(float* c, uint32_t a0, uint32_t a1, uint32_t a2, uint32_t a3,
                                         uint32_t b0, uint32_t b1) {
    asm volatile("mma.sync.aligned.m16n8k16.row.col.f32.bf16.bf16.f32 "
                 "{%0,%1,%2,%3}, {%4,%5,%6,%7}, {%8,%9}, {%0,%1,%2,%3};\n"
                 : "+f"(c[0]), "+f"(c[1]), "+f"(c[2]), "+f"(c[3])
                 : "r"(a0), "r"(a1), "r"(a2), "r"(a3), "r"(b0), "r"(b1));
}

__device__ __forceinline__ void red_add_v4(float* gptr, float4 v) {
    asm volatile("red.global.add.v4.f32 [%0], {%1, %2, %3, %4};"
                 :: "l"(gptr), "f"(v.x), "f"(v.y), "f"(v.z), "f"(v.w) : "memory");
}

// ---------------------------------------------------------------------------
// One dense layer, warp-local. Warp tm owns rows [16tm, 16tm+16). A split pair
// at stride LDA (bf16), W split pair at stride LDW. Epilogue fully in regs:
// bias+SELU, then (LAST ? f32 pair stores to sF stride FS : bf16 split pair
// packed STS.32 to sOb/sOs stride LDO). Ends with __syncwarp().
// ---------------------------------------------------------------------------
template<int COLS, int KDIM, int LDA, int LDW, int LDO, int FS, bool LAST>
__device__ __forceinline__ void mma_layer(
    const __nv_bfloat16* sAb, const __nv_bfloat16* sAs,
    const __nv_bfloat16* sWb, const __nv_bfloat16* sWs,
    const float* sBias,
    __nv_bfloat16* sOb, __nv_bfloat16* sOs, float* sF,
    const int lane, const int tm)
{
    constexpr int NT8 = COLS / 8;
    float c1[NT8][4], c2[NT8][4];
    #pragma unroll
    for (int j = 0; j < NT8; j++)
        #pragma unroll
        for (int e = 0; e < 4; e++) { c1[j][e] = 0.f; c2[j][e] = 0.f; }

    const int g = lane >> 2, t = lane & 3;

    // A fragment lane address: row = 16tm + (lane&15), col half = (lane>>4)*8
    const uint32_t aoff = (uint32_t)(((tm * 16 + (lane & 15)) * LDA + (lane >> 4) * 8) * 2);
    const uint32_t aB = sptr(sAb) + aoff;
    const uint32_t aS = sptr(sAs) + aoff;
    // B fragment lane address: k row = (lane&7) + (lane>>4)*8, n col = ((lane>>3)&1)*8
    const int krow = (lane & 7) + ((lane >> 4) << 3);
    const int ncol = ((lane >> 3) & 1) << 3;
    const uint32_t woff = (uint32_t)((krow * LDW + ncol) * 2);
    const uint32_t wB = sptr(sWb) + woff;
    const uint32_t wS = sptr(sWs) + woff;

    #pragma unroll
    for (int k = 0; k < KDIM / 16; k++) {
        uint32_t a0, a1, a2, a3, x0, x1, x2, x3;
        ldsm_x4(a0, a1, a2, a3, aB + k * 32);
        ldsm_x4(x0, x1, x2, x3, aS + k * 32);
        #pragma unroll
        for (int j2 = 0; j2 < COLS / 16; j2++) {
            uint32_t w0, w1, w2, w3, s0, s1, s2, s3;
            const uint32_t bo = (uint32_t)((k * 16 * LDW + j2 * 16) * 2);
            ldsm_x4_t(w0, w1, w2, w3, wB + bo);
            ldsm_x4_t(s0, s1, s2, s3, wS + bo);
            mma16816(c1[2 * j2],     a0, a1, a2, a3, w0, w2);
            mma16816(c1[2 * j2 + 1], a0, a1, a2, a3, w1, w3);
            mma16816(c2[2 * j2],     a0, a1, a2, a3, s0, s2);
            mma16816(c2[2 * j2],     x0, x1, x2, x3, w0, w2);
            mma16816(c2[2 * j2 + 1], a0, a1, a2, a3, s1, s3);
            mma16816(c2[2 * j2 + 1], x0, x1, x2, x3, w1, w3);
        }
    }

    // register epilogue: c elems map to rows {16tm+g, 16tm+g+8}, cols j*8+2t+{0,1}
    #pragma unroll
    for (int j = 0; j < NT8; j++) {
        const float2 bb = *reinterpret_cast<const float2*>(sBias + j * 8 + 2 * t);
        const float v0 = selu_f(c1[j][0] + c2[j][0] + bb.x);
        const float v1 = selu_f(c1[j][1] + c2[j][1] + bb.y);
        const float v2 = selu_f(c1[j][2] + c2[j][2] + bb.x);
        const float v3 = selu_f(c1[j][3] + c2[j][3] + bb.y);
        const int col = j * 8 + 2 * t;
        if (LAST) {
            *reinterpret_cast<float2*>(sF + (tm * 16 + g) * FS + col)     = make_float2(v0, v1);
            *reinterpret_cast<float2*>(sF + (tm * 16 + g + 8) * FS + col) = make_float2(v2, v3);
        } else {
            uint32_t h01, l01, h23, l23;
            split_pair(v0, v1, h01, l01);
            split_pair(v2, v3, h23, l23);
            *reinterpret_cast<uint32_t*>(sOb + (tm * 16 + g) * LDO + col)     = h01;
            *reinterpret_cast<uint32_t*>(sOs + (tm * 16 + g) * LDO + col)     = l01;
            *reinterpret_cast<uint32_t*>(sOb + (tm * 16 + g + 8) * LDO + col) = h23;
            *reinterpret_cast<uint32_t*>(sOs + (tm * 16 + g + 8) * LDO + col) = l23;
        }
    }
    __syncwarp();
}

// ---------------------------------------------------------------------------
// phi_e smem layout (bytes). Strides: X 136, H/W1/W2 72, W3 40, sF 36 (f32).
// Total 193280 (~188.8 KB). All offsets 128-B aligned.
// ---------------------------------------------------------------------------
#define E_OFF_F    0          // sF fp32 128x36                 (18432)
#define E_OFF_B1   18432
#define E_OFF_B2   18688
#define E_OFF_B3   18944
#define E_OFF_I1   19200
#define E_OFF_I2   19712
#define E_OFF_WB1  20224      // 128x72 bf16                    (18432)
#define E_OFF_WS1  38656
#define E_OFF_WB2  57088      // 64x72                          (9216)
#define E_OFF_WS2  66304
#define E_OFF_WB3  75520      // 64x40                          (5120)
#define E_OFF_WS3  80640
#define E_OFF_XB   85760      // 128x136                        (34816)
#define E_OFF_XS   120576
#define E_OFF_HB   155392     // 128x72                         (18432)
#define E_OFF_HS   173824
#define E_OFF_PART 192256     // 8x32 f32                       (1024)
#define E_SMEM_BYTES 193280

__global__ void __launch_bounds__(256, 1) phi_e_kernel(
    const float* __restrict__ bonds,
    const int* __restrict__ ba1, const int* __restrict__ ba2,
    const float* __restrict__ atoms, const float* __restrict__ state,
    const float* __restrict__ w1, const float* __restrict__ b1,
    const float* __restrict__ w2, const float* __restrict__ b2,
    const float* __restrict__ w3, const float* __restrict__ b3,
    float* __restrict__ out_bonds, int E)
{
    extern __shared__ __align__(16) char smraw[];
    float* sF  = reinterpret_cast<float*>(smraw + E_OFF_F);
    float* sB1 = reinterpret_cast<float*>(smraw + E_OFF_B1);
    float* sB2 = reinterpret_cast<float*>(smraw + E_OFF_B2);
    float* sB3 = reinterpret_cast<float*>(smraw + E_OFF_B3);
    int*   sI1 = reinterpret_cast<int*>(smraw + E_OFF_I1);
    int*   sI2 = reinterpret_cast<int*>(smraw + E_OFF_I2);
    __nv_bfloat16* sWb1 = reinterpret_cast<__nv_bfloat16*>(smraw + E_OFF_WB1);
    __nv_bfloat16* sWs1 = reinterpret_cast<__nv_bfloat16*>(smraw + E_OFF_WS1);
    __nv_bfloat16* sWb2 = reinterpret_cast<__nv_bfloat16*>(smraw + E_OFF_WB2);
    __nv_bfloat16* sWs2 = reinterpret_cast<__nv_bfloat16*>(smraw + E_OFF_WS2);
    __nv_bfloat16* sWb3 = reinterpret_cast<__nv_bfloat16*>(smraw + E_OFF_WB3);
    __nv_bfloat16* sWs3 = reinterpret_cast<__nv_bfloat16*>(smraw + E_OFF_WS3);
    __nv_bfloat16* sXb  = reinterpret_cast<__nv_bfloat16*>(smraw + E_OFF_XB);
    __nv_bfloat16* sXs  = reinterpret_cast<__nv_bfloat16*>(smraw + E_OFF_XS);
    __nv_bfloat16* sHb  = reinterpret_cast<__nv_bfloat16*>(smraw + E_OFF_HB);
    __nv_bfloat16* sHs  = reinterpret_cast<__nv_bfloat16*>(smraw + E_OFF_HS);
    float* sPart = reinterpret_cast<float*>(smraw + E_OFF_PART);

    const int tid = threadIdx.x;
    const int lane = tid & 31, tm = tid >> 5;

    // weights -> padded split pairs, once per CTA
    for (int i = tid; i < 8192; i += 256) {
        const int k = i >> 6, j = i & 63;
        split1(sWb1 + k * 72 + j, sWs1 + k * 72 + j, w1[i]);
    }
    for (int i = tid; i < 4096; i += 256) {
        const int k = i >> 6, j = i & 63;
        split1(sWb2 + k * 72 + j, sWs2 + k * 72 + j, w2[i]);
    }
    for (int i = tid; i < 2048; i += 256) {
        const int k = i >> 5, j = i & 31;
        split1(sWb3 + k * 40 + j, sWs3 + k * 40 + j, w3[i]);
    }
    if (tid < 64) { sB1[tid] = b1[tid]; sB2[tid] = b2[tid]; }
    if (tid < 32) sB3[tid] = b3[tid];
    // zero X/H region once (stale-bits safety for partial strips)
    for (int i = tid * 4; i < (E_OFF_PART - E_OFF_XB); i += 1024)
        *reinterpret_cast<uint32_t*>(smraw + E_OFF_XB + i) = 0;
    __syncthreads();

    const float4* atoms4 = reinterpret_cast<const float4*>(atoms);
    const float4* bonds4 = reinterpret_cast<const float4*>(bonds);
    const float4* state4 = reinterpret_cast<const float4*>(state);

    float csum = 0.f;
    const int numTiles = (E + 127) / 128;
    for (int tile = blockIdx.x; tile < numTiles; tile += gridDim.x) {
        const int e0 = tile * 128;
        const int r0 = tm * 16;
        const int rv = min(16, max(0, E - e0 - r0));   // valid rows in strip

        if (lane < 16 && lane < rv) {
            sI1[r0 + lane] = ba1[e0 + r0 + lane];
            sI2[r0 + lane] = ba2[e0 + r0 + lane];
        }
        __syncwarp();

        // strip-local assembly: X = [a1 | a2 | bond | state], stride 136
        for (int i = lane; i < 128; i += 32) {
            const int el = i >> 3, c = i & 7;
            if (el < rv) {
                const int row = r0 + el;
                const float4 v1 = atoms4[(size_t)sI1[row] * 8 + c];
                const float4 v2 = atoms4[(size_t)sI2[row] * 8 + c];
                const float4 vb = bonds4[(size_t)(e0 + row) * 8 + c];
                const float4 vs = state4[c];
                const int r = row * 136 + c * 4;
                split4(sXb + r,      sXs + r,      v1);
                split4(sXb + r + 32, sXs + r + 32, v2);
                split4(sXb + r + 64, sXs + r + 64, vb);
                split4(sXb + r + 96, sXs + r + 96, vs);
            }
        }
        __syncwarp();

        mma_layer<64, 128, 136, 72,  72,  0, false>(sXb, sXs, sWb1, sWs1, sB1, sHb, sHs, nullptr, lane, tm);
        mma_layer<64,  64,  72, 72, 136,  0, false>(sHb, sHs, sWb2, sWs2, sB2, sXb, sXs, nullptr, lane, tm);
        mma_layer<32,  64, 136, 40,   0, 36, true >(sXb, sXs, sWb3, sWs3, sB3, nullptr, nullptr, sF, lane, tm);

        // strip-local: write bonds_new + vector-scatter
        for (int i = lane; i < 128; i += 32) {
            const int el = i >> 3, c4 = (i & 7) * 4;
            if (el < rv) {
                const int row = r0 + el;
                const float4 v = *reinterpret_cast<const float4*>(sF + row * 36 + c4);
                *reinterpret_cast<float4*>(out_bonds + (size_t)(e0 + row) * 32 + c4) = v;
                red_add_v4(&g_b2a[(size_t)sI1[row] * 32 + c4], v);
            }
        }
        if (lane < 16 && lane < rv) atomicAdd(&g_cnt[sI1[r0 + lane]], 1.0f);

        // column partial sum into per-lane register (lane = col)
        for (int r2 = 0; r2 < rv; r2++) csum += sF[(r0 + r2) * 36 + lane];
        __syncwarp();   // protect sI/sF/X before next iteration overwrites
    }

    // final cross-warp reduction of bond column sums
    sPart[tm * 32 + lane] = csum;
    __syncthreads();
    if (tid < 32) {
        float s = 0.f;
        #pragma unroll
        for (int g2 = 0; g2 < 8; g2++) s += sPart[g2 * 32 + tid];
        atomicAdd(&g_bond_sum[tid], s);
    }
}

// ---------------------------------------------------------------------------
// phi_v smem layout (bytes). X stride 104, H 72, W3 40, sF 36.
// Total 166656 (~162.8 KB).
// ---------------------------------------------------------------------------
#define V_OFF_F    0          // sF fp32 128x36                 (18432)
#define V_OFF_B1   18432
#define V_OFF_B2   18688
#define V_OFF_B3   18944
#define V_OFF_WB1  19200      // 96x72                          (13824)
#define V_OFF_WS1  33024
#define V_OFF_WB2  46848      // 64x72                          (9216)
#define V_OFF_WS2  56064
#define V_OFF_WB3  65280      // 64x40                          (5120)
#define V_OFF_WS3  70400
#define V_OFF_XB   75520      // 128x104                        (26624)
#define V_OFF_XS   102144
#define V_OFF_HB   128768     // 128x72                         (18432)
#define V_OFF_HS   147200
#define V_OFF_PART 165632     // 8x32 f32                       (1024)
#define V_SMEM_BYTES 166656

__global__ void __launch_bounds__(256, 1) phi_v_kernel(
    const float* __restrict__ atoms, const float* __restrict__ state,
    const float* __restrict__ w1, const float* __restrict__ b1,
    const float* __restrict__ w2, const float* __restrict__ b2,
    const float* __restrict__ w3, const float* __restrict__ b3,
    float* __restrict__ out_atoms, int N)
{
    extern __shared__ __align__(16) char smraw[];
    float* sF  = reinterpret_cast<float*>(smraw + V_OFF_F);
    float* sB1 = reinterpret_cast<float*>(smraw + V_OFF_B1);
    float* sB2 = reinterpret_cast<float*>(smraw + V_OFF_B2);
    float* sB3 = reinterpret_cast<float*>(smraw + V_OFF_B3);
    __nv_bfloat16* sWb1 = reinterpret_cast<__nv_bfloat16*>(smraw + V_OFF_WB1);
    __nv_bfloat16* sWs1 = reinterpret_cast<__nv_bfloat16*>(smraw + V_OFF_WS1);
    __nv_bfloat16* sWb2 = reinterpret_cast<__nv_bfloat16*>(smraw + V_OFF_WB2);
    __nv_bfloat16* sWs2 = reinterpret_cast<__nv_bfloat16*>(smraw + V_OFF_WS2);
    __nv_bfloat16* sWb3 = reinterpret_cast<__nv_bfloat16*>(smraw + V_OFF_WB3);
    __nv_bfloat16* sWs3 = reinterpret_cast<__nv_bfloat16*>(smraw + V_OFF_WS3);
    __nv_bfloat16* sXb  = reinterpret_cast<__nv_bfloat16*>(smraw + V_OFF_XB);
    __nv_bfloat16* sXs  = reinterpret_cast<__nv_bfloat16*>(smraw + V_OFF_XS);
    __nv_bfloat16* sHb  = reinterpret_cast<__nv_bfloat16*>(smraw + V_OFF_HB);
    __nv_bfloat16* sHs  = reinterpret_cast<__nv_bfloat16*>(smraw + V_OFF_HS);
    float* sPart = reinterpret_cast<float*>(smraw + V_OFF_PART);

    const int tid = threadIdx.x;
    const int lane = tid & 31, tm = tid >> 5;

    for (int i = tid; i < 6144; i += 256) {
        const int k = i >> 6, j = i & 63;
        split1(sWb1 + k * 72 + j, sWs1 + k * 72 + j, w1[i]);
    }
    for (int i = tid; i < 4096; i += 256) {
        const int k = i >> 6, j = i & 63;
        split1(sWb2 + k * 72 + j, sWs2 + k * 72 + j, w2[i]);
    }
    for (int i = tid; i < 2048; i += 256) {
        const int k = i >> 5, j = i & 31;
        split1(sWb3 + k * 40 + j, sWs3 + k * 40 + j, w3[i]);
    }
    if (tid < 64) { sB1[tid] = b1[tid]; sB2[tid] = b2[tid]; }
    if (tid < 32) sB3[tid] = b3[tid];
    for (int i = tid * 4; i < (V_OFF_PART - V_OFF_XB); i += 1024)
        *reinterpret_cast<uint32_t*>(smraw + V_OFF_XB + i) = 0;
    __syncthreads();

    const float4* atoms4 = reinterpret_cast<const float4*>(atoms);
    const float4* state4 = reinterpret_cast<const float4*>(state);
    const float4* b2a4   = reinterpret_cast<const float4*>(g_b2a);

    float csum = 0.f;
    const int numTiles = (N + 127) / 128;
    for (int tile = blockIdx.x; tile < numTiles; tile += gridDim.x) {
        const int a0 = tile * 128;
        const int r0 = tm * 16;
        const int rv = min(16, max(0, N - a0 - r0));

        // strip-local assembly: X = [b2a/cnt | atom | state], stride 104
        for (int i = lane; i < 128; i += 32) {
            const int el = i >> 3, c = i & 7;
            if (el < rv) {
                const int a = a0 + r0 + el;
                float4 v0;
                {
                    const float inv = 1.0f / g_cnt[a];
                    const float4 tt = b2a4[(size_t)a * 8 + c];
                    v0 = make_float4(tt.x * inv, tt.y * inv, tt.z * inv, tt.w * inv);
                }
                const float4 va = atoms4[(size_t)a * 8 + c];
                const float4 vs = state4[c];
                const int r = (r0 + el) * 104;
                split4(sXb + r + c * 4,      sXs + r + c * 4,      v0);
                split4(sXb + r + 32 + c * 4, sXs + r + 32 + c * 4, va);
                split4(sXb + r + 64 + c * 4, sXs + r + 64 + c * 4, vs);
            }
        }
        __syncwarp();

        mma_layer<64, 96, 104, 72,  72,  0, false>(sXb, sXs, sWb1, sWs1, sB1, sHb, sHs, nullptr, lane, tm);
        mma_layer<64, 64,  72, 72, 104,  0, false>(sHb, sHs, sWb2, sWs2, sB2, sXb, sXs, nullptr, lane, tm);
        mma_layer<32, 64, 104, 40,   0, 36, true >(sXb, sXs, sWb3, sWs3, sB3, nullptr, nullptr, sF, lane, tm);

        for (int i = lane; i < 128; i += 32) {
            const int el = i >> 3, c4 = (i & 7) * 4;
            if (el < rv) {
                const int row = r0 + el;
                const float4 v = *reinterpret_cast<const float4*>(sF + row * 36 + c4);
                *reinterpret_cast<float4*>(out_atoms + (size_t)(a0 + row) * 32 + c4) = v;
            }
        }
        for (int r2 = 0; r2 < rv; r2++) csum += sF[(r0 + r2) * 36 + lane];
        __syncwarp();
    }

    sPart[tm * 32 + lane] = csum;
    __syncthreads();
    if (tid < 32) {
        float s = 0.f;
        #pragma unroll
        for (int g2 = 0; g2 < 8; g2++) s += sPart[g2 * 32 + tid];
        atomicAdd(&g_atom_sum[tid], s);
    }
}

// ---------------------------------------------------------------------------
// phi_u: state MLP 96 -> 64 -> 64 -> 32 (single block, fp32).
// ---------------------------------------------------------------------------
__global__ void phi_u_kernel(
    const float* __restrict__ state,
    const float* __restrict__ w1, const float* __restrict__ b1,
    const float* __restrict__ w2, const float* __restrict__ b2,
    const float* __restrict__ w3, const float* __restrict__ b3,
    float* __restrict__ out_state, int E, int N)
{
    __shared__ float x[96], h1[64], h2[64];
    const int t = threadIdx.x;
    if (t < 32) {
        x[t]      = g_bond_sum[t] / (float)E;
        x[32 + t] = g_atom_sum[t] / (float)N;
        x[64 + t] = state[t];
    }
    __syncthreads();
    if (t < 64) {
        float s = b1[t];
        for (int k = 0; k < 96; k++) s = fmaf(x[k], w1[k * 64 + t], s);
        h1[t] = selu_f(s);
    }
    __syncthreads();
    if (t < 64) {
        float s = b2[t];
        for (int k = 0; k < 64; k++) s = fmaf(h1[k], w2[k * 64 + t], s);
        h2[t] = selu_f(s);
    }
    __syncthreads();
    if (t < 32) {
        float s = b3[t];
        for (int k = 0; k < 64; k++) s = fmaf(h2[k], w3[k * 32 + t], s);
        out_state[t] = selu_f(s);
    }
}

__global__ void zero_scratch_kernel(int N)
{
    const int i = blockIdx.x * blockDim.x + threadIdx.x;
    const int nb4 = N * 8;
    float4* b2a4 = reinterpret_cast<float4*>(g_b2a);
    const float4 z4 = make_float4(0.f, 0.f, 0.f, 0.f);
    if (i < nb4) b2a4[i] = z4;
    if (i < N)  g_cnt[i] = 0.f;
    if (i < 32) { g_bond_sum[i] = 0.f; g_atom_sum[i] = 0.f; }
}

// ---------------------------------------------------------------------------

extern "C" void kernel_launch(void* const* d_in, const int* in_sizes, int n_in,
                              void* d_out, int out_size)
{
    const float* bonds = (const float*)d_in[0];
    const int*   ba1   = (const int*)d_in[1];
    const int*   ba2   = (const int*)d_in[2];
    const float* atoms = (const float*)d_in[3];
    const float* state = (const float*)d_in[4];
    const float* e_w1 = (const float*)d_in[5],  *e_b1 = (const float*)d_in[6];
    const float* e_w2 = (const float*)d_in[7],  *e_b2 = (const float*)d_in[8];
    const float* e_w3 = (const float*)d_in[9],  *e_b3 = (const float*)d_in[10];
    const float* v_w1 = (const float*)d_in[11], *v_b1 = (const float*)d_in[12];
    const float* v_w2 = (const float*)d_in[13], *v_b2 = (const float*)d_in[14];
    const float* v_w3 = (const float*)d_in[15], *v_b3 = (const float*)d_in[16];
    const float* u_w1 = (const float*)d_in[17], *u_b1 = (const float*)d_in[18];
    const float* u_w2 = (const float*)d_in[19], *u_b2 = (const float*)d_in[20];
    const float* u_w3 = (const float*)d_in[21], *u_b3 = (const float*)d_in[22];

    const int E = in_sizes[1];
    const int N = in_sizes[3] / 32;

    float* out_bonds = (float*)d_out;
    float* out_atoms = out_bonds + (size_t)E * 32;
    float* out_state = out_atoms + (size_t)N * 32;

    cudaFuncSetAttribute(phi_e_kernel, cudaFuncAttributeMaxDynamicSharedMemorySize, E_SMEM_BYTES);
    cudaFuncSetAttribute(phi_v_kernel, cudaFuncAttributeMaxDynamicSharedMemorySize, V_SMEM_BYTES);

    const int numTilesE = (E + 127) / 128;
    const int numTilesV = (N + 127) / 128;
    const int gridE = numTilesE < PERSISTENT_GRID ? numTilesE : PERSISTENT_GRID;
    const int gridV = numTilesV < PERSISTENT_GRID ? numTilesV : PERSISTENT_GRID;

    zero_scratch_kernel<<<(N * 8 + 255) / 256, 256>>>(N);
    phi_e_kernel<<<gridE, 256, E_SMEM_BYTES>>>(
        bonds, ba1, ba2, atoms, state,
        e_w1, e_b1, e_w2, e_b2, e_w3, e_b3, out_bonds, E);
    phi_v_kernel<<<gridV, 256, V_SMEM_BYTES>>>(
        atoms, state, v_w1, v_b1, v_w2, v_b2, v_w3, v_b3, out_atoms, N);
    phi_u_kernel<<<1, 96>>>(
        state, u_w1, u_b1, u_w2, u_b2, u_w3, u_b3, out_state, E, N);
}